// round 9
// baseline (speedup 1.0000x reference)
#include <cuda_runtime.h>
#include <math.h>
#include <float.h>

// Problem shape (fixed)
#define Bsz   16
#define Dd    256
#define HW    1024            // H*W = 32*32
#define Kc    8192
#define Nrow  16384           // Bsz*HW
#define NUMEL 4194304         // Bsz*Dd*HW

// GEMM tiling
#define BM 128
#define BN 128
#define KCC 32
#define CGRP 1024             // codes per work unit (8 BN tiles)
#define NTILE  (Nrow / BM)    // 128 row tiles
#define NCG    (Kc / CGRP)    // 8 code groups
#define NUNITS (NTILE * NCG)  // 1024 work units
#define PERSIST_BLOCKS 148
#define NTHREADS 512

// Output layout: [z_q_st (NUMEL)] [vq_loss (1)] [indices (Nrow)] [perplexity (1)]
#define OFF_LOSS  NUMEL
#define OFF_IDX   (NUMEL + 1)
#define OFF_PERP  (NUMEL + 1 + Nrow)

#define GATHER_BLOCKS 4096

typedef unsigned long long u64;

// Device-global scratch (no allocations allowed)
__device__ __align__(16) float g_cbT[(size_t)Dd * Kc];   // codebook transposed [d][c], 8.4MB
__device__ __align__(16) float g_cnorm[Kc];
__device__ float  g_znorm[Nrow];
__device__ u64    g_best[Nrow];         // packed (dist_bits<<32)|idx, combined via atomicMin
__device__ unsigned int g_work;         // work-stealing counter
__device__ double g_part[GATHER_BLOCKS];

// Packed fp32x2 ops (sm_100+). Per-lane IEEE rn — bit-identical to scalar FFMA.
#define FFMA2(d, a, b) asm("fma.rn.f32x2 %0, %1, %2, %0;" : "+l"(d) : "l"(a), "l"(b))
#define SPLAT2(d, x)   asm("mov.b64 %0, {%1, %1};"        : "=l"(d) : "f"(x))
#define UNPK2(lo, hi, v) asm("mov.b64 {%0, %1}, %2;" : "=f"(lo), "=f"(hi) : "l"(v))

// ---------------------------------------------------------------------------
// Transpose codebook [K][D] -> cbT [D][K] (coalesced both sides via smem tile)
__global__ void k_transpose(const float* __restrict__ cb) {
    __shared__ float t[32][33];
    int c0 = blockIdx.x * 32, d0 = blockIdx.y * 32;
    int tx = threadIdx.x, ty = threadIdx.y;   // 32 x 8
    #pragma unroll
    for (int i = 0; i < 32; i += 8)
        t[ty + i][tx] = cb[(size_t)(c0 + ty + i) * Dd + d0 + tx];
    __syncthreads();
    #pragma unroll
    for (int i = 0; i < 32; i += 8)
        g_cbT[(size_t)(d0 + ty + i) * Kc + c0 + tx] = t[tx][ty + i];
}

// ||e_c||^2 in fp64 -> fp32
__global__ void k_cnorm(const float* __restrict__ cb) {
    int c = blockIdx.x * blockDim.x + threadIdx.x;
    const float* p = cb + (size_t)c * Dd;
    double s = 0.0;
    #pragma unroll 8
    for (int d = 0; d < Dd; d++) { float v = p[d]; s += (double)v * (double)v; }
    g_cnorm[c] = (float)s;
}

// ||z_i||^2 ; also resets g_best and the work counter (graph-replay safe)
__global__ void k_znorm(const float* __restrict__ z) {
    int row = blockIdx.x * blockDim.x + threadIdx.x;
    int b = row >> 10, hw = row & 1023;
    const float* p = z + (size_t)b * (Dd * HW) + hw;
    double s = 0.0;
    #pragma unroll 8
    for (int d = 0; d < Dd; d++) { float v = p[(size_t)d * HW]; s += (double)v * (double)v; }
    g_znorm[row] = (float)s;
    g_best[row]  = 0xFFFFFFFFFFFFFFFFull;
    if (row == 0) g_work = 0;
}

// ---------------------------------------------------------------------------
// Persistent fused GEMM (Z @ C^T) + argmin. 148 blocks x 512 threads
// (4 warps/SMSP for latency hiding) work-steal 1024 units (row-tile x
// 1024-code group). 128x128 block tile, 4x8 micro-tile per thread, packed
// f32x2 FFMAs, register prefetch continuous across d0 AND c0 boundaries.
// dist = fl(fl(zn+cn) - 2*dot). Per-unit best combined via atomicMin on
// (dist_bits<<32)|idx — commutative => deterministic; ties -> lowest index,
// matching the reference argmin.
__global__ __launch_bounds__(NTHREADS, 1) void k_argmin(const float* __restrict__ z) {
    __shared__ float As[KCC][BM];     // 16KB, z slab k-major (matches gmem layout)
    __shared__ float Bs[KCC][BN];     // 16KB, code slab from g_cbT, k-major
    __shared__ int   s_unit;

    int tid  = threadIdx.x;
    int colg = tid & 15, rowg = tid >> 4;       // 16 cols-groups x 32 row-groups

    // gmem<->smem slot mapping: 1024 float4 slots per matrix, 2 per thread
    int dls[2], x4s[2];
    #pragma unroll
    for (int it = 0; it < 2; it++) { int s = tid + it * NTHREADS; dls[it] = s >> 5; x4s[it] = (s & 31) << 2; }

    for (;;) {
        __syncthreads();                         // protect smem reuse across units
        if (tid == 0) s_unit = atomicAdd(&g_work, 1u);
        __syncthreads();
        int u = s_unit;
        if (u >= NUNITS) break;

        int tile  = u >> 3;                      // 0..127 row tile
        int cbase = (u & 7) * CGRP;              // 0..7168 step 1024
        int cend  = cbase + CGRP;
        int row0  = tile << 7;
        int b = row0 >> 10, hw0 = row0 & 1023;
        const float* zbase = z + (size_t)b * (Dd * HW) + hw0;   // addr(d, r) = d*HW + r

        float zn[4];
        #pragma unroll
        for (int i = 0; i < 4; i++) zn[i] = g_znorm[row0 + rowg * 4 + i];

        float bestv[4]; int besti[4];
        #pragma unroll
        for (int i = 0; i < 4; i++) { bestv[i] = FLT_MAX; besti[i] = 0; }

        float4 rA[2], rB[2];
        #pragma unroll
        for (int it = 0; it < 2; it++) {         // unit prologue: chunk (d0=0, cbase)
            rA[it] = *(const float4*)(zbase + (size_t)dls[it] * HW + x4s[it]);
            rB[it] = *(const float4*)(g_cbT + (size_t)dls[it] * Kc + cbase + x4s[it]);
        }

        for (int c0 = cbase; c0 < cend; c0 += BN) {
            u64 acc[4][4];                       // 4 rows x 4 col-pairs (fp32x2)
            #pragma unroll
            for (int i = 0; i < 4; i++)
                #pragma unroll
                for (int j = 0; j < 4; j++) acc[i][j] = 0ULL;

            for (int d0 = 0; d0 < Dd; d0 += KCC) {
                __syncthreads();
                #pragma unroll
                for (int it = 0; it < 2; it++) {
                    *(float4*)&As[dls[it]][x4s[it]] = rA[it];
                    *(float4*)&Bs[dls[it]][x4s[it]] = rB[it];
                }
                __syncthreads();
                // prefetch next chunk (wraps d0 -> next c0 within this unit)
                int d0n = d0 + KCC, c0n = c0;
                if (d0n == Dd) { d0n = 0; c0n = c0 + BN; }
                if (c0n < cend) {
                    #pragma unroll
                    for (int it = 0; it < 2; it++) {
                        rA[it] = *(const float4*)(zbase + (size_t)(d0n + dls[it]) * HW + x4s[it]);
                        rB[it] = *(const float4*)(g_cbT + (size_t)(d0n + dls[it]) * Kc + c0n + x4s[it]);
                    }
                }
                #pragma unroll
                for (int k = 0; k < KCC; k++) {
                    float4 a0 = *(const float4*)&As[k][rowg * 4];        // broadcast
                    const u64* bp0 = (const u64*)&Bs[k][colg * 4];
                    const u64* bp1 = (const u64*)&Bs[k][64 + colg * 4];
                    u64 a2[4], bp[4];
                    SPLAT2(a2[0], a0.x); SPLAT2(a2[1], a0.y);
                    SPLAT2(a2[2], a0.z); SPLAT2(a2[3], a0.w);
                    bp[0] = bp0[0]; bp[1] = bp0[1]; bp[2] = bp1[0]; bp[3] = bp1[1];
                    #pragma unroll
                    for (int i = 0; i < 4; i++)
                        #pragma unroll
                        for (int j = 0; j < 4; j++)
                            FFMA2(acc[i][j], a2[i], bp[j]);
                }
            }
            // epilogue: dist + running argmin; pair j2 covers codes (base, base+1)
            #pragma unroll
            for (int j2 = 0; j2 < 4; j2++) {
                int base = c0 + ((j2 < 2) ? (colg * 4 + j2 * 2) : (64 + colg * 4 + (j2 - 2) * 2));
                float cnl = g_cnorm[base], cnh = g_cnorm[base + 1];
                #pragma unroll
                for (int i = 0; i < 4; i++) {
                    float dlo, dhi; UNPK2(dlo, dhi, acc[i][j2]);
                    float t1   = zn[i] + cnl;                 // fl(zn + cn), as reference
                    float dist = fmaf(-2.0f, dlo, t1);        // fl(t1 - 2*dot)
                    if (dist < bestv[i]) { bestv[i] = dist; besti[i] = base; }
                    t1   = zn[i] + cnh;
                    dist = fmaf(-2.0f, dhi, t1);
                    if (dist < bestv[i]) { bestv[i] = dist; besti[i] = base + 1; }
                }
            }
        }

        // cross-thread reduce (overlay onto As/Bs), then one atomic per row
        __syncthreads();
        float (*sv)[BM] = (float(*)[BM])As;      // [16][128] used
        int   (*si)[BM] = (int  (*)[BM])Bs;
        #pragma unroll
        for (int i = 0; i < 4; i++) {
            sv[colg][rowg * 4 + i] = bestv[i];
            si[colg][rowg * 4 + i] = besti[i];
        }
        __syncthreads();
        if (tid < BM) {
            float bv = sv[0][tid]; int bi = si[0][tid];
            #pragma unroll
            for (int g = 1; g < 16; g++) {
                float v = sv[g][tid]; int ix = si[g][tid];
                if (v < bv || (v == bv && ix < bi)) { bv = v; bi = ix; }
            }
            u64 key = ((u64)__float_as_uint(bv) << 32) | (unsigned)bi;  // dist>0 => monotone
            atomicMin(&g_best[row0 + tid], key);
        }
    }
}

// ---------------------------------------------------------------------------
// Gather z_q, emit straight-through output, accumulate loss (deterministic)
__global__ void k_gather(const float* __restrict__ z, const float* __restrict__ cb,
                         float* __restrict__ out) {
    __shared__ double red[256];
    int tid = threadIdx.x;
    double local = 0.0;
    #pragma unroll
    for (int j = 0; j < 4; j++) {
        int e  = blockIdx.x * 256 + tid + j * (NUMEL / 4);
        int hw = e & 1023;
        int d  = (e >> 10) & 255;
        int b  = e >> 18;
        int idx  = (int)(unsigned)(g_best[(b << 10) | hw] & 0xFFFFFFFFull);
        float zq = cb[(size_t)idx * Dd + d];
        float ze = z[e];
        float diff = zq - ze;                 // fl(z_q - z_e)
        out[e] = ze + diff;                   // fl(z_e + fl(z_q - z_e)) == reference STE
        float sq = diff * diff;               // fp32 square like reference
        local += (double)sq;
    }
    red[tid] = local;
    __syncthreads();
    for (int s = 128; s > 0; s >>= 1) {       // fixed-order tree: deterministic
        if (tid < s) red[tid] += red[tid + s];
        __syncthreads();
    }
    if (tid == 0) g_part[blockIdx.x] = red[0];
}

// ---------------------------------------------------------------------------
// Finalize: indices out, vq_loss, perplexity. Single block, deterministic.
__global__ void k_final(float* __restrict__ out) {
    __shared__ int    cnt[Kc];       // 32 KB
    __shared__ double red[256];
    int tid = threadIdx.x;
    for (int c = tid; c < Kc; c += 256) cnt[c] = 0;
    __syncthreads();
    for (int i = tid; i < Nrow; i += 256) {
        int ix = (int)(unsigned)(g_best[i] & 0xFFFFFFFFull);
        atomicAdd(&cnt[ix], 1);      // integer atomics: order-independent
        out[OFF_IDX + i] = (float)ix;
    }
    __syncthreads();

    // vq_loss = L + BETA*L, L = mean((z_q - z_e)^2)
    double s = 0.0;
    for (int p = tid; p < GATHER_BLOCKS; p += 256) s += g_part[p];
    red[tid] = s; __syncthreads();
    for (int st = 128; st > 0; st >>= 1) { if (tid < st) red[tid] += red[tid + st]; __syncthreads(); }
    if (tid == 0) {
        float L = (float)(red[0] / (double)NUMEL);
        out[OFF_LOSS] = L + 0.25f * L;
    }
    __syncthreads();

    // perplexity = exp(-sum p*log(p+1e-10)), p = counts/N
    double ent = 0.0;
    for (int c = tid; c < Kc; c += 256) {
        double p = (double)cnt[c] / (double)Nrow;
        ent += p * log(p + 1e-10);
    }
    red[tid] = ent; __syncthreads();
    for (int st = 128; st > 0; st >>= 1) { if (tid < st) red[tid] += red[tid + st]; __syncthreads(); }
    if (tid == 0) out[OFF_PERP] = (float)exp(-red[0]);
}

// ---------------------------------------------------------------------------
extern "C" void kernel_launch(void* const* d_in, const int* in_sizes, int n_in,
                              void* d_out, int out_size) {
    const float* z  = (const float*)d_in[0];   // z_e: 4,194,304
    const float* cb = (const float*)d_in[1];   // codebook: 2,097,152
    if (n_in >= 2 && in_sizes[0] == Kc * Dd && in_sizes[1] == NUMEL) {
        cb = (const float*)d_in[0];
        z  = (const float*)d_in[1];
    }
    float* out = (float*)d_out;

    k_transpose<<<dim3(Kc / 32, Dd / 32), dim3(32, 8)>>>(cb);
    k_cnorm   <<<Kc / 256, 256>>>(cb);
    k_znorm   <<<Nrow / 256, 256>>>(z);
    k_argmin  <<<PERSIST_BLOCKS, NTHREADS>>>(z);
    k_gather  <<<GATHER_BLOCKS, 256>>>(z, cb, out);
    k_final   <<<1, 256>>>(out);
}

// round 11
// speedup vs baseline: 1.1781x; 1.1781x over previous
#include <cuda_runtime.h>
#include <math.h>
#include <float.h>

// Problem shape (fixed)
#define Bsz   16
#define Dd    256
#define HW    1024            // H*W = 32*32
#define Kc    8192
#define Nrow  16384           // Bsz*HW
#define NUMEL 4194304         // Bsz*Dd*HW

// GEMM tiling
#define BM 128
#define BN 128
#define KCC 32
#define CGRP 512              // codes per work unit (4 BN tiles)
#define NTILE  (Nrow / BM)    // 128 row tiles
#define NCG    (Kc / CGRP)    // 16 code groups
#define NUNITS (NTILE * NCG)  // 2048 work units
#define PERSIST_BLOCKS 296    // 2 CTAs per SM x 148 SMs

// Output layout: [z_q_st (NUMEL)] [vq_loss (1)] [indices (Nrow)] [perplexity (1)]
#define OFF_LOSS  NUMEL
#define OFF_IDX   (NUMEL + 1)
#define OFF_PERP  (NUMEL + 1 + Nrow)

#define GATHER_BLOCKS 4096

typedef unsigned long long u64;

// Device-global scratch (no allocations allowed)
__device__ __align__(16) float g_cbT[(size_t)Dd * Kc];   // codebook transposed [d][c], 8.4MB
__device__ __align__(16) float g_cnorm[Kc];
__device__ float  g_znorm[Nrow];
__device__ u64    g_best[Nrow];         // packed (dist_bits<<32)|idx, combined via atomicMin
__device__ unsigned int g_work;         // work-stealing counter
__device__ double g_part[GATHER_BLOCKS];

// Packed fp32x2 ops (sm_100+). Per-lane IEEE rn — bit-identical to scalar FFMA.
#define FFMA2(d, a, b) asm("fma.rn.f32x2 %0, %1, %2, %0;" : "+l"(d) : "l"(a), "l"(b))
#define SPLAT2(d, x)   asm("mov.b64 %0, {%1, %1};"        : "=l"(d) : "f"(x))
#define UNPK2(lo, hi, v) asm("mov.b64 {%0, %1}, %2;" : "=f"(lo), "=f"(hi) : "l"(v))

// cp.async: gmem -> smem 16B, no staging registers (LDGSTS)
#define CP_ASYNC16(dst_u32, src_ptr) \
    asm volatile("cp.async.cg.shared.global [%0], [%1], 16;" :: "r"(dst_u32), "l"(src_ptr) : "memory")
#define CP_COMMIT() asm volatile("cp.async.commit_group;" ::: "memory")
#define CP_WAIT0()  asm volatile("cp.async.wait_group 0;"  ::: "memory")

// ---------------------------------------------------------------------------
// Transpose codebook [K][D] -> cbT [D][K] (coalesced both sides via smem tile)
__global__ void k_transpose(const float* __restrict__ cb) {
    __shared__ float t[32][33];
    int c0 = blockIdx.x * 32, d0 = blockIdx.y * 32;
    int tx = threadIdx.x, ty = threadIdx.y;   // 32 x 8
    #pragma unroll
    for (int i = 0; i < 32; i += 8)
        t[ty + i][tx] = cb[(size_t)(c0 + ty + i) * Dd + d0 + tx];
    __syncthreads();
    #pragma unroll
    for (int i = 0; i < 32; i += 8)
        g_cbT[(size_t)(d0 + ty + i) * Kc + c0 + tx] = t[tx][ty + i];
}

// ||e_c||^2 in fp64 -> fp32
__global__ void k_cnorm(const float* __restrict__ cb) {
    int c = blockIdx.x * blockDim.x + threadIdx.x;
    const float* p = cb + (size_t)c * Dd;
    double s = 0.0;
    #pragma unroll 8
    for (int d = 0; d < Dd; d++) { float v = p[d]; s += (double)v * (double)v; }
    g_cnorm[c] = (float)s;
}

// ||z_i||^2 ; also resets g_best and the work counter (graph-replay safe)
__global__ void k_znorm(const float* __restrict__ z) {
    int row = blockIdx.x * blockDim.x + threadIdx.x;
    int b = row >> 10, hw = row & 1023;
    const float* p = z + (size_t)b * (Dd * HW) + hw;
    double s = 0.0;
    #pragma unroll 8
    for (int d = 0; d < Dd; d++) { float v = p[(size_t)d * HW]; s += (double)v * (double)v; }
    g_znorm[row] = (float)s;
    g_best[row]  = 0xFFFFFFFFFFFFFFFFull;
    if (row == 0) g_work = 0;
}

// ---------------------------------------------------------------------------
// Persistent fused GEMM (Z @ C^T) + argmin. 296 blocks (2 CTAs/SM) x 256
// threads work-steal 2048 units (row-tile x 512-code group). R8-proven inner
// loop: 128x128 tile, 8x8 micro-tile, packed f32x2 FFMAs + splats. Smem fill
// via cp.async (no staging regs -> fits 128 regs for 2 CTAs/SM; co-resident
// CTA hides load latency). dist = fl(fl(zn+cn) - 2*dot). Per-unit best via
// atomicMin on (dist_bits<<32)|idx — commutative => deterministic; ties ->
// lowest index, matching the reference argmin.
__global__ __launch_bounds__(256, 2) void k_argmin(const float* __restrict__ z) {
    __shared__ float As[KCC][BM];     // 16KB, z slab k-major (matches gmem layout)
    __shared__ float Bs[KCC][BN];     // 16KB, code slab from g_cbT, k-major
    __shared__ int   s_unit;

    int tid  = threadIdx.x;
    int colg = tid & 15, rowg = tid >> 4;       // 16 x 16 thread grid

    // gmem<->smem slot mapping: 1024 float4 slots per matrix, 4 per thread
    int dls[4], x4s[4];
    unsigned sAd[4], sBd[4];
    #pragma unroll
    for (int it = 0; it < 4; it++) {
        int s = tid + it * 256; dls[it] = s >> 5; x4s[it] = (s & 31) << 2;
        sAd[it] = (unsigned)__cvta_generic_to_shared(&As[dls[it]][x4s[it]]);
        sBd[it] = (unsigned)__cvta_generic_to_shared(&Bs[dls[it]][x4s[it]]);
    }

    for (;;) {
        __syncthreads();                         // protect smem reuse across units
        if (tid == 0) s_unit = atomicAdd(&g_work, 1u);
        __syncthreads();
        int u = s_unit;
        if (u >= NUNITS) break;

        int tile  = u >> 4;                      // 0..127 row tile
        int cbase = (u & 15) * CGRP;             // 0..7680 step 512
        int cend  = cbase + CGRP;
        int row0  = tile << 7;
        int b = row0 >> 10, hw0 = row0 & 1023;
        const float* zbase = z + (size_t)b * (Dd * HW) + hw0;   // addr(d, r) = d*HW + r

        float zn[8];
        #pragma unroll
        for (int i = 0; i < 4; i++) {
            zn[i]     = g_znorm[row0 + rowg * 4 + i];
            zn[4 + i] = g_znorm[row0 + 64 + rowg * 4 + i];
        }

        float bestv[8]; int besti[8];
        #pragma unroll
        for (int i = 0; i < 8; i++) { bestv[i] = FLT_MAX; besti[i] = 0; }

        for (int c0 = cbase; c0 < cend; c0 += BN) {
            u64 acc[8][4];                       // 8 rows x 4 col-pairs (fp32x2)
            #pragma unroll
            for (int i = 0; i < 8; i++)
                #pragma unroll
                for (int j = 0; j < 4; j++) acc[i][j] = 0ULL;

            for (int d0 = 0; d0 < Dd; d0 += KCC) {
                __syncthreads();                 // prev chunk compute done
                #pragma unroll
                for (int it = 0; it < 4; it++) {
                    CP_ASYNC16(sAd[it], zbase + (size_t)(d0 + dls[it]) * HW + x4s[it]);
                    CP_ASYNC16(sBd[it], g_cbT + (size_t)(d0 + dls[it]) * Kc + c0 + x4s[it]);
                }
                CP_COMMIT();
                CP_WAIT0();                      // own loads landed (peer CTA computes now)
                __syncthreads();                 // all threads' loads landed
                #pragma unroll
                for (int k = 0; k < KCC; k++) {
                    float4 a0 = *(const float4*)&As[k][rowg * 4];        // broadcast
                    float4 a1 = *(const float4*)&As[k][64 + rowg * 4];
                    const u64* bp0 = (const u64*)&Bs[k][colg * 4];
                    const u64* bp1 = (const u64*)&Bs[k][64 + colg * 4];
                    u64 a2[8], bp[4];
                    SPLAT2(a2[0], a0.x); SPLAT2(a2[1], a0.y); SPLAT2(a2[2], a0.z); SPLAT2(a2[3], a0.w);
                    SPLAT2(a2[4], a1.x); SPLAT2(a2[5], a1.y); SPLAT2(a2[6], a1.z); SPLAT2(a2[7], a1.w);
                    bp[0] = bp0[0]; bp[1] = bp0[1]; bp[2] = bp1[0]; bp[3] = bp1[1];
                    #pragma unroll
                    for (int i = 0; i < 8; i++)
                        #pragma unroll
                        for (int j = 0; j < 4; j++)
                            FFMA2(acc[i][j], a2[i], bp[j]);
                }
            }
            // epilogue: dist + running argmin; pair j2 covers codes (base, base+1)
            #pragma unroll
            for (int j2 = 0; j2 < 4; j2++) {
                int base = c0 + ((j2 < 2) ? (colg * 4 + j2 * 2) : (64 + colg * 4 + (j2 - 2) * 2));
                float cnl = g_cnorm[base], cnh = g_cnorm[base + 1];
                #pragma unroll
                for (int i = 0; i < 8; i++) {
                    float dlo, dhi; UNPK2(dlo, dhi, acc[i][j2]);
                    float t1   = zn[i] + cnl;                 // fl(zn + cn), as reference
                    float dist = fmaf(-2.0f, dlo, t1);        // fl(t1 - 2*dot)
                    if (dist < bestv[i]) { bestv[i] = dist; besti[i] = base; }
                    t1   = zn[i] + cnh;
                    dist = fmaf(-2.0f, dhi, t1);
                    if (dist < bestv[i]) { bestv[i] = dist; besti[i] = base + 1; }
                }
            }
        }

        // cross-thread reduce (overlay onto As/Bs), then one atomic per row
        __syncthreads();
        float (*sv)[BM] = (float(*)[BM])As;
        int   (*si)[BM] = (int  (*)[BM])Bs;
        #pragma unroll
        for (int i = 0; i < 8; i++) {
            int r = (i < 4) ? (rowg * 4 + i) : (64 + rowg * 4 + (i - 4));
            sv[colg][r] = bestv[i];
            si[colg][r] = besti[i];
        }
        __syncthreads();
        if (tid < BM) {
            float bv = sv[0][tid]; int bi = si[0][tid];
            #pragma unroll
            for (int g = 1; g < 16; g++) {
                float v = sv[g][tid]; int ix = si[g][tid];
                if (v < bv || (v == bv && ix < bi)) { bv = v; bi = ix; }
            }
            u64 key = ((u64)__float_as_uint(bv) << 32) | (unsigned)bi;  // dist>0 => monotone
            atomicMin(&g_best[row0 + tid], key);
        }
    }
}

// ---------------------------------------------------------------------------
// Gather z_q, emit straight-through output, accumulate loss (deterministic)
__global__ void k_gather(const float* __restrict__ z, const float* __restrict__ cb,
                         float* __restrict__ out) {
    __shared__ double red[256];
    int tid = threadIdx.x;
    double local = 0.0;
    #pragma unroll
    for (int j = 0; j < 4; j++) {
        int e  = blockIdx.x * 256 + tid + j * (NUMEL / 4);
        int hw = e & 1023;
        int d  = (e >> 10) & 255;
        int b  = e >> 18;
        int idx  = (int)(unsigned)(g_best[(b << 10) | hw] & 0xFFFFFFFFull);
        float zq = cb[(size_t)idx * Dd + d];
        float ze = z[e];
        float diff = zq - ze;                 // fl(z_q - z_e)
        out[e] = ze + diff;                   // fl(z_e + fl(z_q - z_e)) == reference STE
        float sq = diff * diff;               // fp32 square like reference
        local += (double)sq;
    }
    red[tid] = local;
    __syncthreads();
    for (int s = 128; s > 0; s >>= 1) {       // fixed-order tree: deterministic
        if (tid < s) red[tid] += red[tid + s];
        __syncthreads();
    }
    if (tid == 0) g_part[blockIdx.x] = red[0];
}

// ---------------------------------------------------------------------------
// Finalize: indices out, vq_loss, perplexity. Single block, deterministic.
__global__ void k_final(float* __restrict__ out) {
    __shared__ int    cnt[Kc];       // 32 KB
    __shared__ double red[256];
    int tid = threadIdx.x;
    for (int c = tid; c < Kc; c += 256) cnt[c] = 0;
    __syncthreads();
    for (int i = tid; i < Nrow; i += 256) {
        int ix = (int)(unsigned)(g_best[i] & 0xFFFFFFFFull);
        atomicAdd(&cnt[ix], 1);      // integer atomics: order-independent
        out[OFF_IDX + i] = (float)ix;
    }
    __syncthreads();

    // vq_loss = L + BETA*L, L = mean((z_q - z_e)^2)
    double s = 0.0;
    for (int p = tid; p < GATHER_BLOCKS; p += 256) s += g_part[p];
    red[tid] = s; __syncthreads();
    for (int st = 128; st > 0; st >>= 1) { if (tid < st) red[tid] += red[tid + st]; __syncthreads(); }
    if (tid == 0) {
        float L = (float)(red[0] / (double)NUMEL);
        out[OFF_LOSS] = L + 0.25f * L;
    }
    __syncthreads();

    // perplexity = exp(-sum p*log(p+1e-10)), p = counts/N
    double ent = 0.0;
    for (int c = tid; c < Kc; c += 256) {
        double p = (double)cnt[c] / (double)Nrow;
        ent += p * log(p + 1e-10);
    }
    red[tid] = ent; __syncthreads();
    for (int st = 128; st > 0; st >>= 1) { if (tid < st) red[tid] += red[tid + st]; __syncthreads(); }
    if (tid == 0) out[OFF_PERP] = (float)exp(-red[0]);
}

// ---------------------------------------------------------------------------
extern "C" void kernel_launch(void* const* d_in, const int* in_sizes, int n_in,
                              void* d_out, int out_size) {
    const float* z  = (const float*)d_in[0];   // z_e: 4,194,304
    const float* cb = (const float*)d_in[1];   // codebook: 2,097,152
    if (n_in >= 2 && in_sizes[0] == Kc * Dd && in_sizes[1] == NUMEL) {
        cb = (const float*)d_in[0];
        z  = (const float*)d_in[1];
    }
    float* out = (float*)d_out;

    k_transpose<<<dim3(Kc / 32, Dd / 32), dim3(32, 8)>>>(cb);
    k_cnorm   <<<Kc / 256, 256>>>(cb);
    k_znorm   <<<Nrow / 256, 256>>>(z);
    k_argmin  <<<PERSIST_BLOCKS, 256>>>(z);
    k_gather  <<<GATHER_BLOCKS, 256>>>(z, cb, out);
    k_final   <<<1, 256>>>(out);
}